// round 5
// baseline (speedup 1.0000x reference)
#include <cuda_runtime.h>
#include <cuda_bf16.h>
#include <math_constants.h>

// Problem shape (fixed by the reference)
#define L_DIM 1024
#define B_DIM 64
#define H_DIM 1024

#define SPLITS 6                        // -> grid 384 CTAs, up to 3 CTAs/SM, single wave
#define WARPS_PER_BLOCK 8
#define HV 8                            // float4 vectors per thread (H/128)

// Scratch: per-(b,split) context vector + (M, D). ~1.5 MB total.
__device__ float g_ctx[B_DIM * SPLITS * H_DIM];
__device__ float g_m[B_DIM * SPLITS];
__device__ float g_d[B_DIM * SPLITS];
__device__ int   g_cnt[B_DIM];          // zero-initialized; reset by last CTA each run

// ---------------------------------------------------------------------------
// Fused kernel: scores + online softmax (rare-rescale) + weighted accumulation,
// in-block warp combine, last-CTA-per-b cross-split combine.
// grid: (SPLITS, B) = 384 CTAs, block: 256 (8 warps), 3 CTAs/SM.
// ---------------------------------------------------------------------------
__global__ __launch_bounds__(256, 3)
void attn_fused(const float* __restrict__ enc,   // [L, B, H]
                const float* __restrict__ dec,   // [1, B, H]
                float* __restrict__ out)         // [B, H]
{
    const int s    = blockIdx.x;
    const int b    = blockIdx.y;
    const int warp = threadIdx.x >> 5;
    const int lane = threadIdx.x & 31;

    __shared__ float s_dec[H_DIM];                    // 4 KB
    __shared__ float s_acc[WARPS_PER_BLOCK][H_DIM];   // 32 KB
    __shared__ float s_m[WARPS_PER_BLOCK];
    __shared__ float s_d[WARPS_PER_BLOCK];
    __shared__ float s_scale[WARPS_PER_BLOCK];
    __shared__ int   s_is_last;

    // Stage decoder row into smem (frees 32 registers vs reg-resident copy).
    {
        const float4* dec4 = reinterpret_cast<const float4*>(dec + (size_t)b * H_DIM);
        reinterpret_cast<float4*>(s_dec)[threadIdx.x] = dec4[threadIdx.x];
    }
    __syncthreads();
    const float4* sdec4 = reinterpret_cast<const float4*>(s_dec);

    float4 acc[HV];
#pragma unroll
    for (int k = 0; k < HV; k++) acc[k] = make_float4(0.f, 0.f, 0.f, 0.f);
    float m = -CUDART_INF_F;
    float d = 0.f;

    const int l0 = (s * L_DIM) / SPLITS + warp;
    const int l1 = ((s + 1) * L_DIM) / SPLITS;

    for (int l = l0; l < l1; l += WARPS_PER_BLOCK) {
        const float4* e4 =
            reinterpret_cast<const float4*>(enc + ((size_t)l * B_DIM + b) * H_DIM);
        float4 ev[HV];
#pragma unroll
        for (int k = 0; k < HV; k++) ev[k] = __ldcs(&e4[k * 32 + lane]);   // MLP = 8

        // dot(e, dec): per-thread partial (dec via LDS), warp butterfly reduce
        float sc = 0.f;
#pragma unroll
        for (int k = 0; k < HV; k++) {
            float4 dv = sdec4[k * 32 + lane];
            sc = fmaf(ev[k].x, dv.x, sc);
            sc = fmaf(ev[k].y, dv.y, sc);
            sc = fmaf(ev[k].z, dv.z, sc);
            sc = fmaf(ev[k].w, dv.w, sc);
        }
#pragma unroll
        for (int off = 16; off > 0; off >>= 1)
            sc += __shfl_xor_sync(0xffffffffu, sc, off);

        if (sc > m) {
            // Rare path: new max. w = exp(sc - sc) = 1.
            const float alpha = __expf(m - sc);     // 0 on first iteration
            d = fmaf(d, alpha, 1.0f);
            m = sc;
#pragma unroll
            for (int k = 0; k < HV; k++) {
                acc[k].x = fmaf(acc[k].x, alpha, ev[k].x);
                acc[k].y = fmaf(acc[k].y, alpha, ev[k].y);
                acc[k].z = fmaf(acc[k].z, alpha, ev[k].z);
                acc[k].w = fmaf(acc[k].w, alpha, ev[k].w);
            }
        } else {
            // Hot path: no rescale, single exp, 32 FMAs.
            const float w = __expf(sc - m);
            d += w;
#pragma unroll
            for (int k = 0; k < HV; k++) {
                acc[k].x = fmaf(w, ev[k].x, acc[k].x);
                acc[k].y = fmaf(w, ev[k].y, acc[k].y);
                acc[k].z = fmaf(w, ev[k].z, acc[k].z);
                acc[k].w = fmaf(w, ev[k].w, acc[k].w);
            }
        }
    }

    // ---- in-block flash combine of the 8 warp partials ----
#pragma unroll
    for (int k = 0; k < HV; k++)
        *reinterpret_cast<float4*>(&s_acc[warp][k * 128 + lane * 4]) = acc[k];
    if (lane == 0) { s_m[warp] = m; s_d[warp] = d; }
    __syncthreads();

    if (threadIdx.x == 0) {
        float M = -CUDART_INF_F;
#pragma unroll
        for (int w = 0; w < WARPS_PER_BLOCK; w++) M = fmaxf(M, s_m[w]);
        float D = 0.f;
#pragma unroll
        for (int w = 0; w < WARPS_PER_BLOCK; w++) {
            float sc = __expf(s_m[w] - M);
            s_scale[w] = sc;
            D += s_d[w] * sc;
        }
        const int pid = b * SPLITS + s;
        g_m[pid] = M;
        g_d[pid] = D;
    }
    __syncthreads();

    // Each thread reduces 4 h-positions across the 8 warp slots (float4).
    {
        const int h = threadIdx.x * 4;
        float4 sum = make_float4(0.f, 0.f, 0.f, 0.f);
#pragma unroll
        for (int w = 0; w < WARPS_PER_BLOCK; w++) {
            float sc = s_scale[w];
            float4 v = *reinterpret_cast<const float4*>(&s_acc[w][h]);
            sum.x = fmaf(sc, v.x, sum.x);
            sum.y = fmaf(sc, v.y, sum.y);
            sum.z = fmaf(sc, v.z, sum.z);
            sum.w = fmaf(sc, v.w, sum.w);
        }
        const int pid = b * SPLITS + s;
        *reinterpret_cast<float4*>(&g_ctx[(size_t)pid * H_DIM + h]) = sum;
    }

    // ---- last-CTA-per-b cross-split combine ----
    __threadfence();
    if (threadIdx.x == 0)
        s_is_last = (atomicAdd(&g_cnt[b], 1) == SPLITS - 1) ? 1 : 0;
    __syncthreads();
    if (!s_is_last) return;

    __threadfence();   // acquire: order reads of peers' partials after the atomic

    float M = -CUDART_INF_F;
#pragma unroll
    for (int p = 0; p < SPLITS; p++) M = fmaxf(M, g_m[b * SPLITS + p]);
    float D = 0.f;
    float scale[SPLITS];
#pragma unroll
    for (int p = 0; p < SPLITS; p++) {
        scale[p] = __expf(g_m[b * SPLITS + p] - M);
        D += g_d[b * SPLITS + p] * scale[p];
    }
    const float invD = 1.f / D;

    {
        const int h = threadIdx.x * 4;
        float4 sum = make_float4(0.f, 0.f, 0.f, 0.f);
#pragma unroll
        for (int p = 0; p < SPLITS; p++) {
            const float sc = scale[p] * invD;
            float4 v = *reinterpret_cast<const float4*>(
                &g_ctx[((size_t)(b * SPLITS + p)) * H_DIM + h]);
            sum.x = fmaf(sc, v.x, sum.x);
            sum.y = fmaf(sc, v.y, sum.y);
            sum.z = fmaf(sc, v.z, sum.z);
            sum.w = fmaf(sc, v.w, sum.w);
        }
        *reinterpret_cast<float4*>(&out[(size_t)b * H_DIM + h]) = sum;
    }

    if (threadIdx.x == 0) g_cnt[b] = 0;   // reset for next graph replay
}

// ---------------------------------------------------------------------------
extern "C" void kernel_launch(void* const* d_in, const int* in_sizes, int n_in,
                              void* d_out, int out_size)
{
    const float* enc = (const float*)d_in[0];   // [1024, 64, 1024]
    const float* dec = (const float*)d_in[1];   // [1, 64, 1024]
    float* out = (float*)d_out;                 // [64, 1024]

    dim3 grid(SPLITS, B_DIM);
    attn_fused<<<grid, 256>>>(enc, dec, out);
}